// round 14
// baseline (speedup 1.0000x reference)
#include <cuda_runtime.h>
#include <math_constants.h>

// Problem constants
#define BB 4
#define NN 4096
#define F_IN 64
#define N_PROP 64
#define N_DIM 4
#define N_FILT 128
#define KN 39          // neighbors kept (top-40 minus self)
#define FULL 0xFFFFFFFFu
#define QPB 16         // queries per block (8 warps x 2)
#define NBUF 288       // per-query slots: live [0..224), staging [64..288)
#define TILE 2048      // coord tile (2 passes over the batch)

// Scratch (allocation-free rule: __device__ globals)
__device__ float g_features[BB*NN*N_PROP];
__device__ float g_coords[BB*NN*N_DIM];

// ---------------------------------------------------------------------------
// K1: features = x@W_flr + b_flr ; coords = x@W_s + b_s  (unchanged, passing)
// ---------------------------------------------------------------------------
__global__ void __launch_bounds__(256) k_feat(
    const float* __restrict__ x,
    const float* __restrict__ Wf, const float* __restrict__ bf,
    const float* __restrict__ Ws, const float* __restrict__ bs)
{
    __shared__ float Wfs[64*64];
    __shared__ float Wss[64*4];
    __shared__ float xs[32][64];

    int t = threadIdx.x;
    int row0 = blockIdx.x * 32;

    for (int k = t; k < 64*64/4; k += 256) ((float4*)Wfs)[k] = ((const float4*)Wf)[k];
    if (t < 64) ((float4*)Wss)[t] = ((const float4*)Ws)[t];
    for (int k = t; k < 32*64/4; k += 256)
        ((float4*)xs)[k] = ((const float4*)(x + row0 * F_IN))[k];
    __syncthreads();

    int j = t & 63, rg = t >> 6;
    float b0 = bf[j];
    float a[8];
#pragma unroll
    for (int r = 0; r < 8; r++) a[r] = b0;
#pragma unroll
    for (int i = 0; i < 64; i++) {
        float wv = Wfs[i * 64 + j];
#pragma unroll
        for (int r = 0; r < 8; r++)
            a[r] = fmaf(xs[rg*8 + r][i], wv, a[r]);
    }
#pragma unroll
    for (int r = 0; r < 8; r++)
        g_features[(row0 + rg*8 + r) * N_PROP + j] = a[r];

    if (t < 128) {
        int r = t >> 2, c = t & 3;
        float a2 = bs[c];
#pragma unroll
        for (int i = 0; i < 64; i++)
            a2 = fmaf(xs[r][i], Wss[i * 4 + c], a2);
        g_coords[(row0 + r) * N_DIM + c] = a2;
    }
}

// ---------------------------------------------------------------------------
// K2 (FUSED): R11 scan core, coord table tiled (2 x 2048) to shrink smem to
// 75.8K -> 3 blocks/SM; launch_bounds(256,3) caps regs at 84; hot-loop store
// uses 32-bit shared addressing (st.shared.v2.b32) to cut ALU pipe work.
// Capacity: check after each 4-step group, trigger c>96, growth <=128 =>
// live <=224; compact39 staging at [64..64+bs), bs<=224 => max slot 287.
// smem: float4 sc[2048] 32K | uint2 bufs[16][288] 36K | uint hists[16][64] 4K
//       | uint2 dump[8][32] 2K  => 75776 B, 3 blocks/SM
// ---------------------------------------------------------------------------
__device__ __forceinline__ int bin6(uint key) {
    int b = (int)(key >> 22) - 208;
    return max(0, min(63, b));
}

// Exact: keep the 39 lex-smallest (key,idx) of buf[0..M) into buf[0..39)
// (unordered), set *th to boundary-bin upper edge. Warp-collective, M<=224.
__device__ __forceinline__ int compact39(uint2* buf, uint* hist, int M,
                                         int lane, uint lmask, uint* th)
{
    hist[2*lane] = 0u; hist[2*lane + 1] = 0u;
    __syncwarp();
    uint2 e[8];
#pragma unroll
    for (int i = 0; i < 8; i++) {
        int s = lane + 32*i;
        if (s < M) { e[i] = buf[s]; atomicAdd(&hist[bin6(e[i].x)], 1u); }
    }
    __syncwarp();
    uint h0 = hist[2*lane], h1 = hist[2*lane + 1];
    int sum = (int)(h0 + h1), incl = sum;
#pragma unroll
    for (int o = 1; o < 32; o <<= 1) {
        int v = __shfl_up_sync(FULL, incl, o);
        if (lane >= o) incl += v;
    }
    int excl = incl - sum;
    uint ball = __ballot_sync(FULL, excl < KN && KN <= incl);
    int sel = __ffs(ball) - 1;
    int t0 = 0, nb = 0;
    if (lane == sel) {
        if (excl + (int)h0 >= KN) { t0 = 2*lane;     nb = excl; }
        else                      { t0 = 2*lane + 1; nb = excl + (int)h0; }
    }
    t0 = __shfl_sync(FULL, t0, sel);
    nb = __shfl_sync(FULL, nb, sel);
    int need = KN - nb;
    __syncwarp();

    // partition: bin<t0 -> buf[0..nb) (nb<=38<64), bin==t0 -> buf[64..64+bb)
    int ca = 0, bb = 0;
#pragma unroll
    for (int i = 0; i < 8; i++) {
        int s = lane + 32*i;
        bool act = s < M;
        int bn = act ? bin6(e[i].x) : 64;
        bool bel = bn < t0;
        bool bnd = bn == t0;
        uint A = __ballot_sync(FULL, bel);
        uint B = __ballot_sync(FULL, bnd);
        if (bel) buf[ca + __popc(A & lmask)] = e[i];
        if (bnd) buf[64 + bb + __popc(B & lmask)] = e[i];
        ca += __popc(A);
        bb += __popc(B);
    }
    __syncwarp();

    // exact rank within boundary set, fill remaining need slots
    int cpos = ca;                      // == nb
    for (int r0 = 0; r0 < bb; r0 += 32) {
        int s = r0 + lane;
        bool act = s < bb;
        uint2 ee = act ? buf[64 + s] : make_uint2(0u, 0u);
        int rank = 0;
        if (act) {
            for (int i = 0; i < bb; i++) {
                uint2 o = buf[64 + i];          // broadcast read
                rank += (o.x < ee.x) || (o.x == ee.x && o.y < ee.y);
            }
        }
        bool kp = act && rank < need;
        uint Kb = __ballot_sync(FULL, kp);
        if (kp) buf[cpos + __popc(Kb & lmask)] = ee;   // cpos..38 < 64
        cpos += __popc(Kb);
    }
    __syncwarp();
    *th = (t0 >= 63) ? FULL : ((uint)(t0 + 209) << 22);
    return KN;
}

__global__ void __launch_bounds__(256, 3) k_knn_agg(
    const float* __restrict__ x,
    const float* __restrict__ Wo, const float* __restrict__ bo,
    float* __restrict__ out)
{
    extern __shared__ char smem_raw[];
    float4* sc    = (float4*)smem_raw;                        // 32768
    uint2*  bufs  = (uint2*)(smem_raw + 32768);               // 36864
    uint*   hists = (uint*)(smem_raw + 32768 + 36864);        // 4096
    uint2*  dump  = (uint2*)(smem_raw + 32768 + 36864 + 4096);// 2048

    int b = blockIdx.y;
    const float4* cp = (const float4*)(g_coords + b * NN * N_DIM);

    int w    = threadIdx.x >> 5;
    int lane = threadIdx.x & 31;
    int ql0  = 2 * w, ql1 = 2 * w + 1;
    int n0   = blockIdx.x * QPB + ql0;
    int n1   = n0 + 1;
    float4 q0 = __ldg(&cp[n0]);
    float4 q1 = __ldg(&cp[n1]);
    float qn0 = fmaf(q0.x, q0.x, fmaf(q0.y, q0.y, fmaf(q0.z, q0.z, q0.w * q0.w)));
    float qn1 = fmaf(q1.x, q1.x, fmaf(q1.y, q1.y, fmaf(q1.z, q1.z, q1.w * q1.w)));
    float m0x = -2.f*q0.x, m0y = -2.f*q0.y, m0z = -2.f*q0.z, m0w = -2.f*q0.w;
    float m1x = -2.f*q1.x, m1y = -2.f*q1.y, m1z = -2.f*q1.z, m1w = -2.f*q1.w;
    uint2* buf0 = bufs + ql0 * NBUF;
    uint2* buf1 = bufs + ql1 * NBUF;
    uint*  h0   = hists + ql0 * 64;
    uint*  h1   = hists + ql1 * 64;
    uint  buf0s = (uint)__cvta_generic_to_shared(buf0);
    uint  buf1s = (uint)__cvta_generic_to_shared(buf1);
    uint  dmps  = (uint)__cvta_generic_to_shared(dump + w * 32 + lane);
    uint lmask = (1u << lane) - 1u;

    uint th0 = FULL, th1 = FULL;
    int  c0 = 0, c1 = 0;

    for (int tile = 0; tile < 2; tile++) {
        __syncthreads();
        for (int i = threadIdx.x; i < TILE; i += blockDim.x)
            sc[i] = cp[tile * TILE + i];
        __syncthreads();
        int jbase = tile * TILE;

        for (int tt = 0; tt < TILE/128; tt++) {
#pragma unroll
            for (int u = 0; u < 4; u++) {    // branch-free candidate steps
                int jl = lane + 32 * (4*tt + u);
                int j = jbase + jl;
                float4 p = sc[jl];
                float pnj = fmaf(p.x, p.x, fmaf(p.y, p.y, fmaf(p.z, p.z, p.w * p.w)));

                float d0 = pnj + qn0;
                d0 = fmaf(m0x, p.x, d0); d0 = fmaf(m0y, p.y, d0);
                d0 = fmaf(m0z, p.z, d0); d0 = fmaf(m0w, p.w, d0);
                d0 = fmaxf(d0, 0.f);
                uint k0 = (j == n0) ? FULL : __float_as_uint(d0);

                float d1 = pnj + qn1;
                d1 = fmaf(m1x, p.x, d1); d1 = fmaf(m1y, p.y, d1);
                d1 = fmaf(m1z, p.z, d1); d1 = fmaf(m1w, p.w, d1);
                d1 = fmaxf(d1, 0.f);
                uint k1 = (j == n1) ? FULL : __float_as_uint(d1);

                bool a0 = k0 < th0;
                uint A0 = __ballot_sync(FULL, a0);
                uint off0 = a0 ? (buf0s + (uint)(c0 + __popc(A0 & lmask)) * 8u)
                              : dmps;
                asm volatile("st.shared.v2.b32 [%0], {%1, %2};"
                             :: "r"(off0), "r"(k0), "r"((uint)j));
                c0 += __popc(A0);

                bool a1 = k1 < th1;
                uint A1 = __ballot_sync(FULL, a1);
                uint off1 = a1 ? (buf1s + (uint)(c1 + __popc(A1 & lmask)) * 8u)
                              : dmps;
                asm volatile("st.shared.v2.b32 [%0], {%1, %2};"
                             :: "r"(off1), "r"(k1), "r"((uint)j));
                c1 += __popc(A1);
            }
            if ((c0 | c1) > 96) {            // one branch per 4 steps
                if (c0 > 96) c0 = compact39(buf0, h0, c0, lane, lmask, &th0);
                if (c1 > 96) c1 = compact39(buf1, h1, c1, lane, lmask, &th1);
            }
        }
    }
    if (c0 > KN) c0 = compact39(buf0, h0, c0, lane, lmask, &th0);
    if (c1 > KN) c1 = compact39(buf1, h1, c1, lane, lmask, &th1);

    // ---- FUSED epilogue: gather + weighted max/mean + concat + GEMM ----
    const float* gf = g_features + b * NN * N_PROP;
    const float inv = 1.0f / 39.0f;

    float mxa0 = -CUDART_INF_F, mxa1 = -CUDART_INF_F, sa0 = 0.f, sa1 = 0.f;
#pragma unroll 8
    for (int k = 0; k < KN; k++) {
        uint2 e = buf0[k];                       // warp-uniform broadcast
        float wt = __expf(-10.0f * __uint_as_float(e.x));
        float2 f = ((const float2*)(gf + e.y * N_PROP))[lane];
        float v0 = wt * f.x, v1 = wt * f.y;
        mxa0 = fmaxf(mxa0, v0); mxa1 = fmaxf(mxa1, v1);
        sa0 += v0; sa1 += v1;
    }
    float mxb0 = -CUDART_INF_F, mxb1 = -CUDART_INF_F, sb0 = 0.f, sb1 = 0.f;
#pragma unroll 8
    for (int k = 0; k < KN; k++) {
        uint2 e = buf1[k];
        float wt = __expf(-10.0f * __uint_as_float(e.x));
        float2 f = ((const float2*)(gf + e.y * N_PROP))[lane];
        float v0 = wt * f.x, v1 = wt * f.y;
        mxb0 = fmaxf(mxb0, v0); mxb1 = fmaxf(mxb1, v1);
        sb0 += v0; sb1 += v1;
    }

    // stage upd rows in each query's buffer tail (slots 160..256, dead now)
    float* u0 = (float*)(buf0 + 160);
    float* u1 = (float*)(buf1 + 160);
    float2 xv0 = ((const float2*)(x + (b * NN + n0) * F_IN))[lane];
    float2 xv1 = ((const float2*)(x + (b * NN + n1) * F_IN))[lane];
    u0[2*lane] = xv0.x;  u0[2*lane+1] = xv0.y;
    u0[64 + 2*lane] = mxa0; u0[64 + 2*lane+1] = mxa1;
    u0[128 + 2*lane] = sa0 * inv; u0[128 + 2*lane+1] = sa1 * inv;
    u1[2*lane] = xv1.x;  u1[2*lane+1] = xv1.y;
    u1[64 + 2*lane] = mxb0; u1[64 + 2*lane+1] = mxb1;
    u1[128 + 2*lane] = sb0 * inv; u1[128 + 2*lane+1] = sb1 * inv;
    __syncwarp();

    // 2-row GEMM vs W_out (lane owns 4 output columns)
    float4 bv = ((const float4*)bo)[lane];
    float4 a0 = bv, a1 = bv;
#pragma unroll 4
    for (int c = 0; c < 192; c++) {
        float4 wv = ((const float4*)(Wo + c * N_FILT))[lane];
        float v0 = u0[c];                        // smem broadcast
        float v1 = u1[c];
        a0.x = fmaf(v0, wv.x, a0.x); a0.y = fmaf(v0, wv.y, a0.y);
        a0.z = fmaf(v0, wv.z, a0.z); a0.w = fmaf(v0, wv.w, a0.w);
        a1.x = fmaf(v1, wv.x, a1.x); a1.y = fmaf(v1, wv.y, a1.y);
        a1.z = fmaf(v1, wv.z, a1.z); a1.w = fmaf(v1, wv.w, a1.w);
    }
    ((float4*)(out + (b * NN + n0) * N_FILT))[lane] = a0;
    ((float4*)(out + (b * NN + n1) * N_FILT))[lane] = a1;
}

// ---------------------------------------------------------------------------
extern "C" void kernel_launch(void* const* d_in, const int* in_sizes, int n_in,
                              void* d_out, int out_size)
{
    const float* x  = (const float*)d_in[0];
    const float* Wf = (const float*)d_in[1];
    const float* bf = (const float*)d_in[2];
    const float* Ws = (const float*)d_in[3];
    const float* bs = (const float*)d_in[4];
    const float* Wo = (const float*)d_in[5];
    const float* bo = (const float*)d_in[6];
    float* out = (float*)d_out;

    const int knn_smem = 32768 + QPB * NBUF * 8 + QPB * 64 * 4 + 2048; // 75776
    cudaFuncSetAttribute(k_knn_agg, cudaFuncAttributeMaxDynamicSharedMemorySize,
                         knn_smem);

    k_feat<<<BB * NN / 32, 256>>>(x, Wf, bf, Ws, bs);

    dim3 g2(NN / QPB, BB);
    k_knn_agg<<<g2, 256, knn_smem>>>(x, Wo, bo, out);
}

// round 15
// speedup vs baseline: 1.2790x; 1.2790x over previous
#include <cuda_runtime.h>
#include <math_constants.h>

// Problem constants
#define BB 4
#define NN 4096
#define F_IN 64
#define N_PROP 64
#define N_DIM 4
#define N_FILT 128
#define KN 39          // neighbors kept (top-40 minus self)
#define FULL 0xFFFFFFFFu
#define QPB 16         // queries per block (8 warps x 2)
#define NBUF 320       // per-query slots: live [0..256), staging [64..320)

// Scratch (allocation-free rule: __device__ globals)
__device__ float g_features[BB*NN*N_PROP];
__device__ float g_coords[BB*NN*N_DIM];
__device__ int   g_nbr_idx[BB*NN*KN];
__device__ float g_nbr_w[BB*NN*KN];

// ---------------------------------------------------------------------------
// K1: features = x@W_flr + b_flr ; coords = x@W_s + b_s  (unchanged, passing)
// ---------------------------------------------------------------------------
__global__ void __launch_bounds__(256) k_feat(
    const float* __restrict__ x,
    const float* __restrict__ Wf, const float* __restrict__ bf,
    const float* __restrict__ Ws, const float* __restrict__ bs)
{
    __shared__ float Wfs[64*64];
    __shared__ float Wss[64*4];
    __shared__ float xs[32][64];

    int t = threadIdx.x;
    int row0 = blockIdx.x * 32;

    for (int k = t; k < 64*64/4; k += 256) ((float4*)Wfs)[k] = ((const float4*)Wf)[k];
    if (t < 64) ((float4*)Wss)[t] = ((const float4*)Ws)[t];
    for (int k = t; k < 32*64/4; k += 256)
        ((float4*)xs)[k] = ((const float4*)(x + row0 * F_IN))[k];
    __syncthreads();

    int j = t & 63, rg = t >> 6;
    float b0 = bf[j];
    float a[8];
#pragma unroll
    for (int r = 0; r < 8; r++) a[r] = b0;
#pragma unroll
    for (int i = 0; i < 64; i++) {
        float wv = Wfs[i * 64 + j];
#pragma unroll
        for (int r = 0; r < 8; r++)
            a[r] = fmaf(xs[rg*8 + r][i], wv, a[r]);
    }
#pragma unroll
    for (int r = 0; r < 8; r++)
        g_features[(row0 + rg*8 + r) * N_PROP + j] = a[r];

    if (t < 128) {
        int r = t >> 2, c = t & 3;
        float a2 = bs[c];
#pragma unroll
        for (int i = 0; i < 64; i++)
            a2 = fmaf(xs[r][i], Wss[i * 4 + c], a2);
        g_coords[(row0 + r) * N_DIM + c] = a2;
    }
}

// ---------------------------------------------------------------------------
// K2: R11 scan core (exact online-threshold top-39, 2 queries/warp, branch-
// free 4-step body). CHANGED: mid-scan compactions are LIGHT (histogram ->
// keep bins <= t0 in place, tighten th; no rank loop). One exact compact at
// the end. Exact: discarded entries have key >= new th; buffer always holds
// every candidate seen with key < th.
// smem: float4 sc[4096] 64K | uint2 bufs[16][320] 40K | uint hists[16][64] 4K
//       | uint2 dump[8][32] 2K  => 110.6K, 2 blocks/SM
// ---------------------------------------------------------------------------
__device__ __forceinline__ int bin6(uint key) {
    int b = (int)(key >> 22) - 208;
    return max(0, min(63, b));
}

// Shared: histogram buf[0..M) into hist, find boundary bin t0 (cumulative
// count reaches KN). Returns t0; *pc0 = this lane's even-bin count (unused).
__device__ __forceinline__ int find_t0_buf(const uint2* e, int cnt_act,
                                           uint* hist, int M, int lane)
{
    hist[2*lane] = 0u; hist[2*lane + 1] = 0u;
    __syncwarp();
#pragma unroll
    for (int i = 0; i < 8; i++)
        if (i < cnt_act) atomicAdd(&hist[bin6(e[i].x)], 1u);
    __syncwarp();
    uint h0 = hist[2*lane], h1 = hist[2*lane + 1];
    int sum = (int)(h0 + h1), incl = sum;
#pragma unroll
    for (int o = 1; o < 32; o <<= 1) {
        int v = __shfl_up_sync(FULL, incl, o);
        if (lane >= o) incl += v;
    }
    int excl = incl - sum;
    uint ball = __ballot_sync(FULL, excl < KN && KN <= incl);
    int sel = __ffs(ball) - 1;
    int t0 = 0;
    if (lane == sel) t0 = (excl + (int)h0 >= KN) ? 2*lane : 2*lane + 1;
    return __shfl_sync(FULL, t0, sel);
}

// LIGHT: keep all entries with bin <= t0, compacted to front; tighten th.
// No rank loop. Warp-collective, M <= 256.
__device__ __forceinline__ int compact_light(uint2* buf, uint* hist, int M,
                                             int lane, uint lmask, uint* th)
{
    uint2 e[8];
    int cnt_act = 0;
#pragma unroll
    for (int i = 0; i < 8; i++) {
        int s = lane + 32*i;
        if (s < M) { e[i] = buf[s]; cnt_act = i + 1; }
    }
    int t0 = find_t0_buf(e, cnt_act, hist, M, lane);
    __syncwarp();

    int ck = 0;
#pragma unroll
    for (int i = 0; i < 8; i++) {
        bool keep = (i < cnt_act) && (bin6(e[i].x) <= t0);
        uint K = __ballot_sync(FULL, keep);
        if (keep) buf[ck + __popc(K & lmask)] = e[i];
        ck += __popc(K);
    }
    __syncwarp();
    *th = (t0 >= 63) ? FULL : ((uint)(t0 + 209) << 22);
    return ck;
}

// EXACT: keep the 39 lex-smallest of buf[0..M) into buf[0..39). Final only.
__device__ __forceinline__ int compact39(uint2* buf, uint* hist, int M,
                                         int lane, uint lmask, uint* th)
{
    hist[2*lane] = 0u; hist[2*lane + 1] = 0u;
    __syncwarp();
    uint2 e[8];
#pragma unroll
    for (int i = 0; i < 8; i++) {
        int s = lane + 32*i;
        if (s < M) { e[i] = buf[s]; atomicAdd(&hist[bin6(e[i].x)], 1u); }
    }
    __syncwarp();
    uint h0 = hist[2*lane], h1 = hist[2*lane + 1];
    int sum = (int)(h0 + h1), incl = sum;
#pragma unroll
    for (int o = 1; o < 32; o <<= 1) {
        int v = __shfl_up_sync(FULL, incl, o);
        if (lane >= o) incl += v;
    }
    int excl = incl - sum;
    uint ball = __ballot_sync(FULL, excl < KN && KN <= incl);
    int sel = __ffs(ball) - 1;
    int t0 = 0, nb = 0;
    if (lane == sel) {
        if (excl + (int)h0 >= KN) { t0 = 2*lane;     nb = excl; }
        else                      { t0 = 2*lane + 1; nb = excl + (int)h0; }
    }
    t0 = __shfl_sync(FULL, t0, sel);
    nb = __shfl_sync(FULL, nb, sel);
    int need = KN - nb;
    __syncwarp();

    int ca = 0, bb = 0;
#pragma unroll
    for (int i = 0; i < 8; i++) {
        int s = lane + 32*i;
        bool act = s < M;
        int bn = act ? bin6(e[i].x) : 64;
        bool bel = bn < t0;
        bool bnd = bn == t0;
        uint A = __ballot_sync(FULL, bel);
        uint B = __ballot_sync(FULL, bnd);
        if (bel) buf[ca + __popc(A & lmask)] = e[i];
        if (bnd) buf[64 + bb + __popc(B & lmask)] = e[i];
        ca += __popc(A);
        bb += __popc(B);
    }
    __syncwarp();

    int cpos = ca;                      // == nb
    for (int r0 = 0; r0 < bb; r0 += 32) {
        int s = r0 + lane;
        bool act = s < bb;
        uint2 ee = act ? buf[64 + s] : make_uint2(0u, 0u);
        int rank = 0;
        if (act) {
            for (int i = 0; i < bb; i++) {
                uint2 o = buf[64 + i];          // broadcast read
                rank += (o.x < ee.x) || (o.x == ee.x && o.y < ee.y);
            }
        }
        bool kp = act && rank < need;
        uint Kb = __ballot_sync(FULL, kp);
        if (kp) buf[cpos + __popc(Kb & lmask)] = ee;
        cpos += __popc(Kb);
    }
    __syncwarp();
    *th = (t0 >= 63) ? FULL : ((uint)(t0 + 209) << 22);
    return KN;
}

__global__ void __launch_bounds__(256, 2) k_knn()
{
    extern __shared__ char smem_raw[];
    float4* sc    = (float4*)smem_raw;                        // 65536
    uint2*  bufs  = (uint2*)(smem_raw + 65536);               // 40960
    uint*   hists = (uint*)(smem_raw + 65536 + 40960);        // 4096
    uint2*  dump  = (uint2*)(smem_raw + 65536 + 40960 + 4096);// 2048

    int b = blockIdx.y;
    const float4* cp = (const float4*)(g_coords + b * NN * N_DIM);
    for (int i = threadIdx.x; i < NN; i += blockDim.x) sc[i] = cp[i];
    __syncthreads();

    int w    = threadIdx.x >> 5;
    int lane = threadIdx.x & 31;
    int ql0  = 2 * w, ql1 = 2 * w + 1;
    int n0   = blockIdx.x * QPB + ql0;
    int n1   = n0 + 1;
    float4 q0 = sc[n0];
    float4 q1 = sc[n1];
    float qn0 = fmaf(q0.x, q0.x, fmaf(q0.y, q0.y, fmaf(q0.z, q0.z, q0.w * q0.w)));
    float qn1 = fmaf(q1.x, q1.x, fmaf(q1.y, q1.y, fmaf(q1.z, q1.z, q1.w * q1.w)));
    float m0x = -2.f*q0.x, m0y = -2.f*q0.y, m0z = -2.f*q0.z, m0w = -2.f*q0.w;
    float m1x = -2.f*q1.x, m1y = -2.f*q1.y, m1z = -2.f*q1.z, m1w = -2.f*q1.w;
    uint2* buf0 = bufs + ql0 * NBUF;
    uint2* buf1 = bufs + ql1 * NBUF;
    uint*  h0   = hists + ql0 * 64;
    uint*  h1   = hists + ql1 * 64;
    uint2* dmp  = dump + w * 32 + lane;
    uint lmask = (1u << lane) - 1u;

    uint th0 = FULL, th1 = FULL;
    int  c0 = 0, c1 = 0;

    for (int tt = 0; tt < 32; tt++) {
#pragma unroll
        for (int u = 0; u < 4; u++) {        // branch-free candidate steps
            int j = lane + 32 * (4*tt + u);
            float4 p = sc[j];
            float pnj = fmaf(p.x, p.x, fmaf(p.y, p.y, fmaf(p.z, p.z, p.w * p.w)));

            float d0 = pnj + qn0;
            d0 = fmaf(m0x, p.x, d0); d0 = fmaf(m0y, p.y, d0);
            d0 = fmaf(m0z, p.z, d0); d0 = fmaf(m0w, p.w, d0);
            d0 = fmaxf(d0, 0.f);
            uint k0 = (j == n0) ? FULL : __float_as_uint(d0);

            float d1 = pnj + qn1;
            d1 = fmaf(m1x, p.x, d1); d1 = fmaf(m1y, p.y, d1);
            d1 = fmaf(m1z, p.z, d1); d1 = fmaf(m1w, p.w, d1);
            d1 = fmaxf(d1, 0.f);
            uint k1 = (j == n1) ? FULL : __float_as_uint(d1);

            bool a0 = k0 < th0;
            uint A0 = __ballot_sync(FULL, a0);
            uint2* dst0 = a0 ? (buf0 + c0 + __popc(A0 & lmask)) : dmp;
            *dst0 = make_uint2(k0, (uint)j);
            c0 += __popc(A0);

            bool a1 = k1 < th1;
            uint A1 = __ballot_sync(FULL, a1);
            uint2* dst1 = a1 ? (buf1 + c1 + __popc(A1 & lmask)) : dmp;
            *dst1 = make_uint2(k1, (uint)j);
            c1 += __popc(A1);
        }
        if ((c0 | c1) > 128) {               // one branch per 4 iterations
            if (c0 > 128) {
                c0 = compact_light(buf0, h0, c0, lane, lmask, &th0);
                if (c0 > 96) c0 = compact39(buf0, h0, c0, lane, lmask, &th0);
            }
            if (c1 > 128) {
                c1 = compact_light(buf1, h1, c1, lane, lmask, &th1);
                if (c1 > 96) c1 = compact39(buf1, h1, c1, lane, lmask, &th1);
            }
        }
    }
    if (c0 > KN) c0 = compact39(buf0, h0, c0, lane, lmask, &th0);
    if (c1 > KN) c1 = compact39(buf1, h1, c1, lane, lmask, &th1);

    int base0 = (b * NN + n0) * KN;
    int base1 = (b * NN + n1) * KN;
    for (int s = lane; s < KN; s += 32) {
        uint2 e0 = buf0[s];
        g_nbr_idx[base0 + s] = (int)e0.y;
        g_nbr_w[base0 + s]   = __expf(-10.0f * __uint_as_float(e0.x));
        uint2 e1 = buf1[s];
        g_nbr_idx[base1 + s] = (int)e1.y;
        g_nbr_w[base1 + s]   = __expf(-10.0f * __uint_as_float(e1.x));
    }
}

// ---------------------------------------------------------------------------
// K3: weighted gather -> max/mean -> concat -> @W_out + b_out  (unchanged)
// ---------------------------------------------------------------------------
__global__ void __launch_bounds__(256) k_agg(
    const float* __restrict__ x,
    const float* __restrict__ Wo, const float* __restrict__ bo,
    float* __restrict__ out)
{
    __shared__ float upd[32][192];
    int warp = threadIdx.x >> 5, lane = threadIdx.x & 31;
    int q0 = blockIdx.x * 32 + warp * 4;
    const float inv = 1.0f / 39.0f;

#pragma unroll
    for (int qq = 0; qq < 4; qq++) {
        int r = q0 + qq;
        const float* fb = g_features + (r >> 12) * NN * N_PROP;
        int bk = r * KN;
        float mx0 = -CUDART_INF_F, mx1 = -CUDART_INF_F, s0 = 0.f, s1 = 0.f;
#pragma unroll 8
        for (int k = 0; k < KN; k++) {
            int   jj = __ldg(&g_nbr_idx[bk + k]);
            float wt = __ldg(&g_nbr_w[bk + k]);
            float2 f = ((const float2*)(fb + jj * N_PROP))[lane];
            float v0 = wt * f.x, v1 = wt * f.y;
            mx0 = fmaxf(mx0, v0); mx1 = fmaxf(mx1, v1);
            s0 += v0; s1 += v1;
        }
        float2 xv = ((const float2*)(x + r * F_IN))[lane];
        int ql = warp * 4 + qq;
        upd[ql][2*lane]         = xv.x;
        upd[ql][2*lane + 1]     = xv.y;
        upd[ql][64 + 2*lane]    = mx0;
        upd[ql][64 + 2*lane+1]  = mx1;
        upd[ql][128 + 2*lane]   = s0 * inv;
        upd[ql][128 + 2*lane+1] = s1 * inv;
    }
    __syncwarp();

    float4 bv = ((const float4*)bo)[lane];
    float4 a0 = bv, a1 = bv, a2 = bv, a3 = bv;
    int ql0 = warp * 4;
#pragma unroll 4
    for (int c = 0; c < 192; c++) {
        float4 wv = ((const float4*)(Wo + c * N_FILT))[lane];
        float u0 = upd[ql0 + 0][c];
        float u1 = upd[ql0 + 1][c];
        float u2 = upd[ql0 + 2][c];
        float u3 = upd[ql0 + 3][c];
        a0.x = fmaf(u0, wv.x, a0.x); a0.y = fmaf(u0, wv.y, a0.y);
        a0.z = fmaf(u0, wv.z, a0.z); a0.w = fmaf(u0, wv.w, a0.w);
        a1.x = fmaf(u1, wv.x, a1.x); a1.y = fmaf(u1, wv.y, a1.y);
        a1.z = fmaf(u1, wv.z, a1.z); a1.w = fmaf(u1, wv.w, a1.w);
        a2.x = fmaf(u2, wv.x, a2.x); a2.y = fmaf(u2, wv.y, a2.y);
        a2.z = fmaf(u2, wv.z, a2.z); a2.w = fmaf(u2, wv.w, a2.w);
        a3.x = fmaf(u3, wv.x, a3.x); a3.y = fmaf(u3, wv.y, a3.y);
        a3.z = fmaf(u3, wv.z, a3.z); a3.w = fmaf(u3, wv.w, a3.w);
    }
    ((float4*)(out + (q0 + 0) * N_FILT))[lane] = a0;
    ((float4*)(out + (q0 + 1) * N_FILT))[lane] = a1;
    ((float4*)(out + (q0 + 2) * N_FILT))[lane] = a2;
    ((float4*)(out + (q0 + 3) * N_FILT))[lane] = a3;
}

// ---------------------------------------------------------------------------
extern "C" void kernel_launch(void* const* d_in, const int* in_sizes, int n_in,
                              void* d_out, int out_size)
{
    const float* x  = (const float*)d_in[0];
    const float* Wf = (const float*)d_in[1];
    const float* bf = (const float*)d_in[2];
    const float* Ws = (const float*)d_in[3];
    const float* bs = (const float*)d_in[4];
    const float* Wo = (const float*)d_in[5];
    const float* bo = (const float*)d_in[6];
    float* out = (float*)d_out;

    const int knn_smem = 65536 + QPB * NBUF * 8 + QPB * 64 * 4 + 2048; // 112640
    cudaFuncSetAttribute(k_knn, cudaFuncAttributeMaxDynamicSharedMemorySize,
                         knn_smem);

    k_feat<<<BB * NN / 32, 256>>>(x, Wf, bf, Ws, bs);

    dim3 g2(NN / QPB, BB);
    k_knn<<<g2, 256, knn_smem>>>();

    k_agg<<<BB * NN / 32, 256>>>(x, Wo, bo, out);
}